// round 14
// baseline (speedup 1.0000x reference)
#include <cuda_runtime.h>
#include <cuda_bf16.h>

#define N_NODES 50000
#define N_EDGES 800000
#define D_IN    128
#define HF      64
#define GB      782            // ceil(50000/64) for gemm (64 nodes/block)
#define AGB     6250           // ceil(50000/8) for agg (8 warps/block, warp=node)
#define GSTRIDE (GB * 256)
#define GEMM_SMEM (2 * 64 * 132 * 4)
#define CSR_BLOCKS  1024       // must be co-resident: 256thr, low regs -> 8/SM*148=1184
#define CSR_THREADS (CSR_BLOCKS * 256)

// Static scratch (allocation is forbidden)
__device__ float g_ft[N_NODES * HF];
__device__ int   g_count[N_NODES];     // zero-init; k_csr re-zeroes each replay
__device__ int   g_off[N_NODES];
__device__ int   g_cnt[N_NODES];
__device__ int   g_cursor[N_NODES];
__device__ int   g_srcs[N_EDGES];
__device__ int   g_total;
__device__ int   g_sync1, g_sync2;     // zero-init; self-resetting each replay

// Packed fp32x2 FMA (Blackwell FFMA2, PTX-only)
#define FMA2(acc, a, b) \
    asm("fma.rn.f32x2 %0, %1, %2, %0;" : "+l"(acc) : "l"(a), "l"(b))

__device__ __forceinline__ float hsum(unsigned long long v) {
    float a, b; asm("mov.b64 {%0,%1}, %2;" : "=f"(a), "=f"(b) : "l"(v));
    return a + b;
}
__device__ __forceinline__ unsigned long long fpack2(float x) {
    unsigned long long v; asm("mov.b64 %0, {%1,%1};" : "=l"(v) : "f"(x));
    return v;
}
__device__ __forceinline__ void funpack(unsigned long long v, float& a, float& b) {
    asm("mov.b64 {%0,%1}, %2;" : "=f"(a), "=f"(b) : "l"(v));
}

// ---------------------------------------------------------------------------
// K1: ft = feat @ W ([N,128]@[128,64]), 4x4 register tile, 64 nodes/block,
// fused dst histogram (4-pass stride loop). Also resets g_total.
// ---------------------------------------------------------------------------
__global__ __launch_bounds__(256) void k_gemm(const float* __restrict__ feat,
                                              const float* __restrict__ W,
                                              const int* __restrict__ dst) {
    extern __shared__ float sm[];
    float* sWt = sm;                 // [64][132]
    float* sft = sm + 64 * 132;      // [64][132]

    int tid  = threadIdx.x;
    int gtid = blockIdx.x * 256 + tid;
    if (gtid == 0) g_total = 0;
    for (int e = gtid; e < N_EDGES; e += GSTRIDE)
        atomicAdd(&g_count[dst[e]], 1);

    for (int idx = tid; idx < D_IN * HF; idx += 256) {
        int k = idx >> 6, c = idx & 63;
        sWt[c * 132 + k] = W[idx];
    }
    int node0 = blockIdx.x * 64;
    const float4* fv = (const float4*)feat;
    float4* sf4 = (float4*)sft;
    for (int idx = tid; idx < 64 * 32; idx += 256) {
        int r = idx >> 5, s = idx & 31;
        int n = node0 + r;
        sf4[r * 33 + s] = (n < N_NODES) ? fv[(size_t)n * 32 + s]
                                        : make_float4(0.f, 0.f, 0.f, 0.f);
    }
    __syncthreads();

    int cg = tid & 15, ng = tid >> 4;
    const ulonglong2* wb = (const ulonglong2*)sWt;
    const ulonglong2* ab = (const ulonglong2*)sft;
    int wo[4], ao[4];
    #pragma unroll
    for (int i = 0; i < 4; i++) wo[i] = (cg + 16 * i) * 33;
    #pragma unroll
    for (int r = 0; r < 4; r++) ao[r] = (4 * ng + r) * 33;

    unsigned long long acc[4][4];
    #pragma unroll
    for (int i = 0; i < 4; i++)
        #pragma unroll
        for (int r = 0; r < 4; r++) acc[i][r] = 0ull;

    #pragma unroll 2
    for (int k = 0; k < 32; k++) {
        ulonglong2 w[4], a[4];
        #pragma unroll
        for (int i = 0; i < 4; i++) w[i] = wb[wo[i] + k];
        #pragma unroll
        for (int r = 0; r < 4; r++) a[r] = ab[ao[r] + k];
        #pragma unroll
        for (int i = 0; i < 4; i++)
            #pragma unroll
            for (int r = 0; r < 4; r++) {
                FMA2(acc[i][r], a[r].x, w[i].x);
                FMA2(acc[i][r], a[r].y, w[i].y);
            }
    }

    #pragma unroll
    for (int r = 0; r < 4; r++) {
        int n = node0 + 4 * ng + r;
        if (n < N_NODES) {
            #pragma unroll
            for (int i = 0; i < 4; i++)
                g_ft[(size_t)n * 64 + cg + 16 * i] = hsum(acc[i][r]);
        }
    }
}

// ---------------------------------------------------------------------------
// K2: fused CSR build — alloc (atomic-cursor segments, g_count re-zero) then
// a device-wide barrier, then placement. CSR_BLOCKS=1024 is guaranteed
// co-resident (256 thr, ~20 regs, no smem -> 8 blocks/SM * 148 = 1184), so
// the counter-spin barrier cannot deadlock. Counters self-reset: the last
// arriver at the exit counter zeroes both, restoring state for replay.
// ---------------------------------------------------------------------------
__global__ __launch_bounds__(256, 8) void k_csr(const int* __restrict__ src,
                                                const int* __restrict__ dst) {
    int tid = blockIdx.x * 256 + threadIdx.x;

    // Phase A: segment allocation
    for (int i = tid; i < N_NODES; i += CSR_THREADS) {
        int cnt = g_count[i];
        g_count[i] = 0;                        // restore invariant for replay
        int off = atomicAdd(&g_total, cnt);
        g_off[i]    = off;
        g_cnt[i]    = cnt;
        g_cursor[i] = off;
    }
    __syncthreads();

    // Grid barrier (release)
    if (threadIdx.x == 0) {
        __threadfence();
        atomicAdd(&g_sync1, 1);
        while (atomicAdd(&g_sync1, 0) < CSR_BLOCKS) __nanosleep(64);
    }
    __syncthreads();
    __threadfence();                           // acquire

    // Phase B: placement
    for (int e = tid; e < N_EDGES; e += CSR_THREADS) {
        int pos = atomicAdd(&g_cursor[dst[e]], 1);
        g_srcs[pos] = src[e];
    }
    __syncthreads();

    // Exit: last arriver resets both counters (everyone else is past all reads)
    if (threadIdx.x == 0) {
        __threadfence();
        int p = atomicAdd(&g_sync2, 1);
        if (p == CSR_BLOCKS - 1) { g_sync1 = 0; g_sync2 = 0; }
    }
}

// ---------------------------------------------------------------------------
// K3: fused score + softmax + aggregate. ONE WARP PER NODE.
// 32 lanes = 2 edges x 16 lanes; lane j owns float4 #j (2 L1 lines/edge, the
// floor). 32-bit addressing; unpredicated full-pair path; packed f32x2
// weighted accumulation; x4 unroll = 4 gathers in flight per lane.
// launch_bounds(256,6) -> <=42 regs, 75% occupancy.
// out[d] = (sum_e exp(e)*ft[src_e]) / sum_e exp(e)   (max-shift cancels)
// ---------------------------------------------------------------------------
__global__ __launch_bounds__(256, 6) void k_agg(float* __restrict__ out) {
    const unsigned FULL = 0xffffffffu;
    int warp = (blockIdx.x * 256 + threadIdx.x) >> 5;  // node id
    if (warp >= N_NODES) return;
    int lane = threadIdx.x & 31;
    int j    = lane & 15;          // float4 slot within 256B row
    int e    = lane >> 4;          // edge slot 0/1

    const float4* __restrict__ ftv = (const float4*)g_ft;
    float4 b = ftv[warp * 16 + j];

    int beg = g_off[warp], cnt = g_cnt[warp];
    unsigned long long accA = 0ull, accB = 0ull;       // packed {x,y},{z,w}
    float den = 0.f;

#define EDGEF(A) do {                                                 \
        float p = (A).x * b.x + (A).y 	* b.y + (A).z * b.z + (A).w * b.w; \
        p += __shfl_xor_sync(FULL, p, 1);                             \
        p += __shfl_xor_sync(FULL, p, 2);                             \
        float ex = __expf(p * 0.25f);                                 \
        unsigned long long ep = fpack2(ex);                           \
        unsigned long long axy, azw;                                  \
        asm("mov.b64 %0, {%1,%2};" : "=l"(axy) : "f"((A).x), "f"((A).y)); \
        asm("mov.b64 %0, {%1,%2};" : "=l"(azw) : "f"((A).z), "f"((A).w)); \
        FMA2(accA, axy, ep);                                          \
        FMA2(accB, azw, ep);                                          \
        den += ex;                                                    \
    } while (0)

    for (int k0 = 0; k0 < cnt; k0 += 32) {
        int lim = cnt - k0; if (lim > 32) lim = 32;
        int myidx = (lane < lim) ? g_srcs[beg + k0 + lane] : 0;  // coalesced
        int npair = lim >> 1;

        int t = 0;
        for (; t + 4 <= npair; t += 4) {               // 8 edges, 4 loads in flight
            int s0 = __shfl_sync(FULL, myidx, 2 * t + e);
            int s1 = __shfl_sync(FULL, myidx, 2 * t + 2 + e);
            int s2 = __shfl_sync(FULL, myidx, 2 * t + 4 + e);
            int s3 = __shfl_sync(FULL, myidx, 2 * t + 6 + e);
            float4 a0 = ftv[s0 * 16 + j];
            float4 a1 = ftv[s1 * 16 + j];
            float4 a2 = ftv[s2 * 16 + j];
            float4 a3 = ftv[s3 * 16 + j];
            EDGEF(a0); EDGEF(a1); EDGEF(a2); EDGEF(a3);
        }
        for (; t < npair; ++t) {
            int s0 = __shfl_sync(FULL, myidx, 2 * t + e);
            float4 a0 = ftv[s0 * 16 + j];
            EDGEF(a0);
        }
        if (lim & 1) {                                 // peeled odd edge
            int s0 = __shfl_sync(FULL, myidx, lim - 1);
            float4 a0 = ftv[s0 * 16 + j];
            float p = a0.x * b.x + a0.y * b.y + a0.z * b.z + a0.w * b.w;
            p += __shfl_xor_sync(FULL, p, 1);
            p += __shfl_xor_sync(FULL, p, 2);
            float ex = (e == 0) ? __expf(p * 0.25f) : 0.f;  // count once
            unsigned long long ep = fpack2(ex);
            unsigned long long axy, azw;
            asm("mov.b64 %0, {%1,%2};" : "=l"(axy) : "f"(a0.x), "f"(a0.y));
            asm("mov.b64 %0, {%1,%2};" : "=l"(azw) : "f"(a0.z), "f"(a0.w));
            FMA2(accA, axy, ep);
            FMA2(accB, azw, ep);
            den += ex;
        }
    }
#undef EDGEF

    // combine the two 16-lane halves (same j in both halves)
    float ax, ay, az, aw;
    funpack(accA, ax, ay);
    funpack(accB, az, aw);
    ax += __shfl_xor_sync(FULL, ax, 16);
    ay += __shfl_xor_sync(FULL, ay, 16);
    az += __shfl_xor_sync(FULL, az, 16);
    aw += __shfl_xor_sync(FULL, aw, 16);
    den += __shfl_xor_sync(FULL, den, 16);

    if (lane < 16) {
        float inv = (den > 0.f) ? (1.f / den) : 0.f;   // isolated node -> zeros
        ((float4*)out)[warp * 16 + j] =
            make_float4(ax * inv, ay * inv, az * inv, aw * inv);
    }
}

// ---------------------------------------------------------------------------
extern "C" void kernel_launch(void* const* d_in, const int* in_sizes, int n_in,
                              void* d_out, int out_size) {
    const float* feat = (const float*)d_in[0];
    const float* W    = (const float*)d_in[1];
    const int*   src  = (const int*)d_in[2];
    const int*   dst  = (const int*)d_in[3];
    float* out = (float*)d_out;

    cudaFuncSetAttribute(k_gemm, cudaFuncAttributeMaxDynamicSharedMemorySize,
                         GEMM_SMEM);
    k_gemm<<<GB, 256, GEMM_SMEM>>>(feat, W, dst);
    k_csr <<<CSR_BLOCKS, 256>>>(src, dst);
    k_agg <<<AGB, 256>>>(out);
}

// round 15
// speedup vs baseline: 1.3570x; 1.3570x over previous
#include <cuda_runtime.h>
#include <cuda_bf16.h>

#define N_NODES 50000
#define N_EDGES 800000
#define D_IN    128
#define HF      64
#define NB      196            // ceil(50000/256)
#define GB      782            // ceil(50000/64) for gemm (64 nodes/block)
#define AGB     6250           // ceil(50000/8) for agg (8 warps/block, warp=node)
#define GSTRIDE (GB * 256)
#define GEMM_SMEM (64 * 132 * 4)    // W only: 33.8KB

// Static scratch (allocation is forbidden)
__device__ float g_ft[N_NODES * HF];
__device__ int   g_count[N_NODES];     // zero-init; k_alloc re-zeroes each replay
__device__ int   g_off[N_NODES];
__device__ int   g_cnt[N_NODES];
__device__ int   g_cursor[N_NODES];
__device__ int   g_srcs[N_EDGES];
__device__ int   g_total;

// Packed fp32x2 FMA (Blackwell FFMA2, PTX-only)
#define FMA2(acc, a, b) \
    asm("fma.rn.f32x2 %0, %1, %2, %0;" : "+l"(acc) : "l"(a), "l"(b))

__device__ __forceinline__ float hsum(unsigned long long v) {
    float a, b; asm("mov.b64 {%0,%1}, %2;" : "=f"(a), "=f"(b) : "l"(v));
    return a + b;
}

// ---------------------------------------------------------------------------
// K1: ft = feat @ W ([N,128]@[128,64]), 4x4 register tile, 64 nodes/block.
// W transposed+padded in smem (33.8KB -> 4 blocks/SM); feat rows read
// DIRECTLY from global: each row is reused by 16 threads within the block,
// which L1 serves (32KB working set). No feat staging, single __syncthreads.
// dst histogram fused (4-pass stride loop); also resets g_total.
// ---------------------------------------------------------------------------
__global__ __launch_bounds__(256) void k_gemm(const float* __restrict__ feat,
                                              const float* __restrict__ W,
                                              const int* __restrict__ dst) {
    extern __shared__ float sWt[];   // [64][132]

    int tid  = threadIdx.x;
    int gtid = blockIdx.x * 256 + tid;
    if (gtid == 0) g_total = 0;
    for (int e = gtid; e < N_EDGES; e += GSTRIDE)
        atomicAdd(&g_count[dst[e]], 1);

    for (int idx = tid; idx < D_IN * HF; idx += 256) {
        int k = idx >> 6, c = idx & 63;
        sWt[c * 132 + k] = W[idx];
    }
    __syncthreads();

    int cg = tid & 15, ng = tid >> 4;
    int node0 = blockIdx.x * 64;

    const ulonglong2* wb = (const ulonglong2*)sWt;     // 33 units/row
    const ulonglong2* fg = (const ulonglong2*)feat;    // 32 units/row (global)
    int wo[4];
    #pragma unroll
    for (int i = 0; i < 4; i++) wo[i] = (cg + 16 * i) * 33;

    int nrow[4];
    #pragma unroll
    for (int r = 0; r < 4; r++) {
        int n = node0 + 4 * ng + r;
        nrow[r] = (n < N_NODES) ? n : (N_NODES - 1);   // clamp loads, guard stores
    }

    unsigned long long acc[4][4];
    #pragma unroll
    for (int i = 0; i < 4; i++)
        #pragma unroll
        for (int r = 0; r < 4; r++) acc[i][r] = 0ull;

    #pragma unroll 4
    for (int k = 0; k < 32; k++) {                     // 32 chunks x 4 floats = K=128
        ulonglong2 w[4], a[4];
        #pragma unroll
        for (int r = 0; r < 4; r++) a[r] = fg[nrow[r] * 32 + k];   // L1-resident
        #pragma unroll
        for (int i = 0; i < 4; i++) w[i] = wb[wo[i] + k];
        #pragma unroll
        for (int i = 0; i < 4; i++)
            #pragma unroll
            for (int r = 0; r < 4; r++) {
                FMA2(acc[i][r], a[r].x, w[i].x);
                FMA2(acc[i][r], a[r].y, w[i].y);
            }
    }

    #pragma unroll
    for (int r = 0; r < 4; r++) {
        int n = node0 + 4 * ng + r;
        if (n < N_NODES) {
            #pragma unroll
            for (int i = 0; i < 4; i++)
                g_ft[n * 64 + cg + 16 * i] = hsum(acc[i][r]);      // coalesced
        }
    }
}

// ---------------------------------------------------------------------------
// K2: segment allocation via global atomic cursor; re-zero g_count for replay.
// ---------------------------------------------------------------------------
__global__ void k_alloc() {
    int i = blockIdx.x * 256 + threadIdx.x;
    if (i < N_NODES) {
        int cnt = g_count[i];
        g_count[i] = 0;
        int off = atomicAdd(&g_total, cnt);
        g_off[i]    = off;
        g_cnt[i]    = cnt;
        g_cursor[i] = off;
    }
}

// ---------------------------------------------------------------------------
// K3: place src ids into per-dst segments
// ---------------------------------------------------------------------------
__global__ void k_place(const int* __restrict__ src, const int* __restrict__ dst) {
    int e = blockIdx.x * 256 + threadIdx.x;            // exact: 3125*256
    int pos = atomicAdd(&g_cursor[dst[e]], 1);
    g_srcs[pos] = src[e];
}

// ---------------------------------------------------------------------------
// K4: fused score + softmax + aggregate. ONE WARP PER NODE. (R13 version,
// the measured-best: 34.0us.) 32 lanes = 2 edges x 16 lanes; lane j owns
// float4 #j (2 L1 lines/edge floor). 32-bit addressing; unpredicated
// full-pair fast path; single odd edge peeled; x4 unroll (4 gathers in
// flight). out[d] = (sum_e exp(e)*ft[src_e]) / sum_e exp(e)
// ---------------------------------------------------------------------------
__global__ __launch_bounds__(256) void k_agg(float* __restrict__ out) {
    const unsigned FULL = 0xffffffffu;
    int warp = (blockIdx.x * 256 + threadIdx.x) >> 5;  // node id
    if (warp >= N_NODES) return;
    int lane = threadIdx.x & 31;
    int j    = lane & 15;          // float4 slot within 256B row
    int e    = lane >> 4;          // edge slot 0/1

    const float4* __restrict__ ftv = (const float4*)g_ft;
    float4 b = ftv[warp * 16 + j];

    int beg = g_off[warp], cnt = g_cnt[warp];
    float4 acc = make_float4(0.f, 0.f, 0.f, 0.f);
    float den = 0.f;

#define EDGEF(A) do {                                                 \
        float p = (A).x * b.x + (A).y * b.y + (A).z * b.z + (A).w * b.w; \
        p += __shfl_xor_sync(FULL, p, 1);                             \
        p += __shfl_xor_sync(FULL, p, 2);                             \
        float ex = __expf(p * 0.25f);                                 \
        acc.x += ex * (A).x; acc.y += ex * (A).y;                     \
        acc.z += ex * (A).z; acc.w += ex * (A).w;                     \
        den += ex;                                                    \
    } while (0)

    for (int k0 = 0; k0 < cnt; k0 += 32) {
        int lim = cnt - k0; if (lim > 32) lim = 32;
        int myidx = (lane < lim) ? g_srcs[beg + k0 + lane] : 0;  // coalesced
        int npair = lim >> 1;                          // full pairs only

        int t = 0;
        for (; t + 4 <= npair; t += 4) {               // 8 edges, 4 loads in flight
            int s0 = __shfl_sync(FULL, myidx, 2 * t + e);
            int s1 = __shfl_sync(FULL, myidx, 2 * t + 2 + e);
            int s2 = __shfl_sync(FULL, myidx, 2 * t + 4 + e);
            int s3 = __shfl_sync(FULL, myidx, 2 * t + 6 + e);
            float4 a0 = ftv[s0 * 16 + j];
            float4 a1 = ftv[s1 * 16 + j];
            float4 a2 = ftv[s2 * 16 + j];
            float4 a3 = ftv[s3 * 16 + j];
            EDGEF(a0); EDGEF(a1); EDGEF(a2); EDGEF(a3);
        }
        for (; t < npair; ++t) {
            int s0 = __shfl_sync(FULL, myidx, 2 * t + e);
            float4 a0 = ftv[s0 * 16 + j];
            EDGEF(a0);
        }
        if (lim & 1) {                                 // peeled odd edge
            int s0 = __shfl_sync(FULL, myidx, lim - 1);
            float4 a0 = ftv[s0 * 16 + j];
            float p = a0.x * b.x + a0.y * b.y + a0.z * b.z + a0.w * b.w;
            p += __shfl_xor_sync(FULL, p, 1);
            p += __shfl_xor_sync(FULL, p, 2);
            float ex = (e == 0) ? __expf(p * 0.25f) : 0.f;  // count once
            acc.x += ex * a0.x; acc.y += ex * a0.y;
            acc.z += ex * a0.z; acc.w += ex * a0.w;
            den += ex;
        }
    }
#undef EDGEF

    // combine the two 16-lane halves (same j in both halves)
    acc.x += __shfl_xor_sync(FULL, acc.x, 16);
    acc.y += __shfl_xor_sync(FULL, acc.y, 16);
    acc.z += __shfl_xor_sync(FULL, acc.z, 16);
    acc.w += __shfl_xor_sync(FULL, acc.w, 16);
    den   += __shfl_xor_sync(FULL, den,   16);

    if (lane < 16) {
        float inv = (den > 0.f) ? (1.f / den) : 0.f;   // isolated node -> zeros
        ((float4*)out)[warp * 16 + j] =
            make_float4(acc.x * inv, acc.y * inv, acc.z * inv, acc.w * inv);
    }
}

// ---------------------------------------------------------------------------
extern "C" void kernel_launch(void* const* d_in, const int* in_sizes, int n_in,
                              void* d_out, int out_size) {
    const float* feat = (const float*)d_in[0];
    const float* W    = (const float*)d_in[1];
    const int*   src  = (const int*)d_in[2];
    const int*   dst  = (const int*)d_in[3];
    float* out = (float*)d_out;

    k_gemm <<<GB, 256, GEMM_SMEM>>>(feat, W, dst);
    k_alloc<<<NB, 256>>>();
    k_place<<<N_EDGES / 256, 256>>>(src, dst);
    k_agg  <<<AGB, 256>>>(out);
}